// round 1
// baseline (speedup 1.0000x reference)
#include <cuda_runtime.h>

// Shapes (fixed by the problem)
namespace {
constexpr int kB = 2, kNP = 4, kN = 64, kP = 24, kCin = 16, kC = 32, kT = 96;
constexpr int kRows = kB * kNP * kN * kP;                                // 12288 h-rows
constexpr long long kAttElems = (long long)kB * kN * kN * kT * kC;       // 25165824
}

// Scratch for h = x @ W, laid out (B*6144, 32) row-major (1.5 MB)
__device__ float g_h[kRows * kC];

// Kernel 1: h[row, c] = sum_k x[row, k] * W[k, c]   (row = flat (b, s*1536+i*24+p))
__global__ void h_kernel(const float* __restrict__ x, const float* __restrict__ W) {
    int gid = blockIdx.x * 256 + threadIdx.x;     // exactly 393216 threads
    int c = gid & 31;
    int row = gid >> 5;
    const float* xr = x + row * kCin;
    float acc = 0.f;
#pragma unroll
    for (int k = 0; k < kCin; ++k)
        acc = fmaf(__ldg(xr + k), __ldg(W + k * kC + c), acc);
    g_h[gid] = acc;
}

// Kernel 2: fused outer-product -> LeakyReLU -> *adj -> softmax(channel) ->
//           attention store + row-sum over j -> h_prime = elu(sum * h_flat)
// Block: (b,s,p) x 8 i's (one warp per i). Lane owns j=lane and j=lane+32,
// full 32-channel softmax in registers (no max-subtract: values bounded).
__global__ void __launch_bounds__(256, 2)
att_kernel(const float* __restrict__ adj, float* __restrict__ out) {
    __shared__ float hs[kN * 33];        // 64 h rows, padded stride 33 (conflict-free)
    __shared__ float ps[8][32 * 33];     // per-warp partial-sum transpose buffer

    const int tid  = threadIdx.x;
    const int warp = tid >> 5;
    const int lane = tid & 31;

    const int p  = blockIdx.x % kP;
    const int bs = blockIdx.x / kP;
    const int s  = bs & 3;
    const int b  = bs >> 2;
    const int i  = (int)blockIdx.y * 8 + warp;

    // Stage the 64 rows h[b, s, j, p, :] for this (b,s,p)
    const float* hbase = g_h + (b * 6144 + s * 1536 + p) * 32;
#pragma unroll
    for (int r = 0; r < 8; ++r) {
        int idx = tid + r * 256;
        int jj = idx >> 5, cc = idx & 31;
        hs[jj * 33 + cc] = hbase[jj * 768 + cc];   // row j is at +j*24*32
    }
    __syncthreads();

    // h_i vector in registers (broadcast reads, conflict-free)
    float hi[kC];
#pragma unroll
    for (int c = 0; c < kC; ++c) hi[c] = hs[i * 33 + c];

    const int t = p * 4 + s;   // attention time index: t = p*NP + s
    float* ob = out + (((long long)(b * kN + i) * kN) * kT + t) * kC;  // + j*T*C per j

    float rsum[kC];
#pragma unroll
    for (int half = 0; half < 2; ++half) {
        const int j = lane + half * 32;
        const float a = __ldg(adj + i * kN + j);
        float e[kC];
        float sum = 0.f;
#pragma unroll
        for (int c = 0; c < kC; ++c) {
            float v = hi[c] * hs[j * 33 + c];
            v = fmaxf(v, 0.2f * v) * a;            // LeakyReLU(0.2) then * adj
            float ev = __expf(v);                  // no max-subtract: |v| <= ~30
            e[c] = ev;
            sum += ev;
        }
        const float inv = __frcp_rn(sum);
        float4* dst = (float4*)(ob + j * (kT * kC));
#pragma unroll
        for (int q = 0; q < 8; ++q) {
            float4 o;
            o.x = e[4*q+0] * inv; o.y = e[4*q+1] * inv;
            o.z = e[4*q+2] * inv; o.w = e[4*q+3] * inv;
            if (half == 0) {
                rsum[4*q+0] = o.x; rsum[4*q+1] = o.y;
                rsum[4*q+2] = o.z; rsum[4*q+3] = o.w;
            } else {
                rsum[4*q+0] += o.x; rsum[4*q+1] += o.y;
                rsum[4*q+2] += o.z; rsum[4*q+3] += o.w;
            }
            dst[q] = o;                             // one full 128B line per j
        }
    }

    // Cross-lane reduction of the 32-vector rsum via padded-smem transpose.
    // Write: lane -> row lane (banks (lane+c)%32, conflict-free per step).
    float* myps = ps[warp];
#pragma unroll
    for (int c = 0; c < kC; ++c) myps[lane * 33 + c] = rsum[c];
    __syncwarp();
    float tot = 0.f;
#pragma unroll
    for (int l = 0; l < 32; ++l) tot += myps[l * 33 + lane];   // lane = channel

    // h_flat uses the OTHER (s,p) decomposition of t: t = s_h*24 + p_h
    const int sh = t / kP, ph = t % kP;
    const float hv = g_h[(b * 6144 + sh * 1536 + i * kP + ph) * 32 + lane];
    const float hp = tot * hv;
    const float res = hp > 0.f ? hp : expm1f(hp);   // ELU(alpha=1)
    out[kAttElems + ((long long)(b * kN + i) * kT + t) * kC + lane] = res;
}

extern "C" void kernel_launch(void* const* d_in, const int* in_sizes, int n_in,
                              void* d_out, int out_size) {
    const float* x   = (const float*)d_in[0];
    const float* adj = (const float*)d_in[1];
    const float* W   = (const float*)d_in[2];
    // d_in[3] = W_c is unused by the reference computation.
    float* out = (float*)d_out;

    h_kernel<<<(kRows * kC) / 256, 256>>>(x, W);

    dim3 grid(kB * kNP * kP, kN / 8);   // (192, 8) blocks, 256 threads
    att_kernel<<<grid, 256>>>(adj, out);
}

// round 2
// speedup vs baseline: 2.1339x; 2.1339x over previous
#include <cuda_runtime.h>

namespace {
constexpr int kB = 2, kNP = 4, kN = 64, kP = 24, kCin = 16, kC = 32, kT = 96;
constexpr int kRows = kB * kNP * kN * kP;                                // 12288
constexpr long long kAttElems = (long long)kB * kN * kN * kT * kC;       // 25165824
constexpr int kPad = 36;  // smem row stride (floats): 16B-aligned, conflict-free
}

__device__ float g_h[kRows * kC];   // h = x @ W, (B*6144, 32) row-major

// Kernel 1: h[row, c] = sum_k x[row, k] * W[k, c]
__global__ void h_kernel(const float* __restrict__ x, const float* __restrict__ W) {
    int gid = blockIdx.x * 256 + threadIdx.x;
    int c = gid & 31;
    int row = gid >> 5;
    const float4* xr = (const float4*)(x + row * kCin);
    float4 a0 = __ldg(xr), a1 = __ldg(xr + 1), a2 = __ldg(xr + 2), a3 = __ldg(xr + 3);
    float acc = 0.f;
    acc = fmaf(a0.x, __ldg(W +  0 * kC + c), acc);
    acc = fmaf(a0.y, __ldg(W +  1 * kC + c), acc);
    acc = fmaf(a0.z, __ldg(W +  2 * kC + c), acc);
    acc = fmaf(a0.w, __ldg(W +  3 * kC + c), acc);
    acc = fmaf(a1.x, __ldg(W +  4 * kC + c), acc);
    acc = fmaf(a1.y, __ldg(W +  5 * kC + c), acc);
    acc = fmaf(a1.z, __ldg(W +  6 * kC + c), acc);
    acc = fmaf(a1.w, __ldg(W +  7 * kC + c), acc);
    acc = fmaf(a2.x, __ldg(W +  8 * kC + c), acc);
    acc = fmaf(a2.y, __ldg(W +  9 * kC + c), acc);
    acc = fmaf(a2.z, __ldg(W + 10 * kC + c), acc);
    acc = fmaf(a2.w, __ldg(W + 11 * kC + c), acc);
    acc = fmaf(a3.x, __ldg(W + 12 * kC + c), acc);
    acc = fmaf(a3.y, __ldg(W + 13 * kC + c), acc);
    acc = fmaf(a3.z, __ldg(W + 14 * kC + c), acc);
    acc = fmaf(a3.w, __ldg(W + 15 * kC + c), acc);
    g_h[gid] = acc;
}

// Kernel 2: warp = (b,s,i,p). 8-lane group owns one j (4 j's per warp-iter),
// lane owns 4 consecutive channels. Softmax denom via 3-stage shuffle butterfly.
__global__ void __launch_bounds__(256)
att_kernel(const float* __restrict__ adj, float* __restrict__ out) {
    __shared__ float hs[kN * kPad];   // 64 rows of h[b,s,j,p,:], stride 36
    __shared__ float adjs[8 * kN];    // adj rows for this block's 8 i's

    const int tid  = threadIdx.x;
    const int warp = tid >> 5;
    const int lane = tid & 31;
    const int lg   = lane & 7;        // channel group: c = 4*lg .. 4*lg+3
    const int grp  = lane >> 3;       // which j within a 4-j iteration

    const int p  = blockIdx.x % kP;
    const int bs = blockIdx.x / kP;
    const int s  = bs & 3;
    const int b  = bs >> 2;
    const int i0 = (int)blockIdx.y * 8;
    const int i  = i0 + warp;

    // Stage h rows (2048 floats = 512 float4); row j at +j*768 floats
    const float4* hb = (const float4*)(g_h + (b * 6144 + s * 1536 + p) * 32);
#pragma unroll
    for (int r = 0; r < 2; ++r) {
        int idx = tid + r * 256;           // 0..511
        int jj = idx >> 3, q = idx & 7;
        float4 v = __ldg(hb + jj * 192 + q);
        *(float4*)(hs + jj * kPad + q * 4) = v;
    }
    // Stage 8 adjacency rows
#pragma unroll
    for (int r = 0; r < 2; ++r) {
        int idx = tid + r * 256;
        adjs[idx] = __ldg(adj + (i0 + (idx >> 6)) * kN + (idx & 63));
    }
    __syncthreads();

    // h_i channels owned by this lane (same for all iterations)
    const float4 hiv = *(const float4*)(hs + i * kPad + lg * 4);

    const int t = p * kNP + s;
    float* ob = out + (((long long)(b * kN + i) * kN) * kT + t) * kC;

    float rs0 = 0.f, rs1 = 0.f, rs2 = 0.f, rs3 = 0.f;
#pragma unroll
    for (int jg = 0; jg < 16; ++jg) {
        const int j = jg * 4 + grp;
        const float4 hj = *(const float4*)(hs + j * kPad + lg * 4);
        const float a = adjs[warp * kN + j];
        float v0 = hiv.x * hj.x; v0 = fmaxf(v0, 0.2f * v0) * a;
        float v1 = hiv.y * hj.y; v1 = fmaxf(v1, 0.2f * v1) * a;
        float v2 = hiv.z * hj.z; v2 = fmaxf(v2, 0.2f * v2) * a;
        float v3 = hiv.w * hj.w; v3 = fmaxf(v3, 0.2f * v3) * a;
        float e0 = __expf(v0), e1 = __expf(v1), e2 = __expf(v2), e3 = __expf(v3);
        float sl = (e0 + e1) + (e2 + e3);
        sl += __shfl_xor_sync(0xffffffffu, sl, 1);
        sl += __shfl_xor_sync(0xffffffffu, sl, 2);
        sl += __shfl_xor_sync(0xffffffffu, sl, 4);
        const float inv = __frcp_rn(sl);
        float4 o;
        o.x = e0 * inv; o.y = e1 * inv; o.z = e2 * inv; o.w = e3 * inv;
        rs0 += o.x; rs1 += o.y; rs2 += o.z; rs3 += o.w;
        *(float4*)(ob + j * (kT * kC) + lg * 4) = o;   // coalesced 128B per j
    }

    // Reduce rsum across the 4 j-groups (lane bits 3,4)
    rs0 += __shfl_xor_sync(0xffffffffu, rs0, 8);
    rs1 += __shfl_xor_sync(0xffffffffu, rs1, 8);
    rs2 += __shfl_xor_sync(0xffffffffu, rs2, 8);
    rs3 += __shfl_xor_sync(0xffffffffu, rs3, 8);
    rs0 += __shfl_xor_sync(0xffffffffu, rs0, 16);
    rs1 += __shfl_xor_sync(0xffffffffu, rs1, 16);
    rs2 += __shfl_xor_sync(0xffffffffu, rs2, 16);
    rs3 += __shfl_xor_sync(0xffffffffu, rs3, 16);

    if (grp == 0) {   // lanes 0..7 hold full channel sums for c = 4*lg..4*lg+3
        const int sh = t / kP, ph = t % kP;   // h_flat decomposition of t
        const float4 hv = *(const float4*)(g_h +
            (b * 6144 + sh * 1536 + i * kP + ph) * 32 + lg * 4);
        float h0 = rs0 * hv.x, h1 = rs1 * hv.y, h2 = rs2 * hv.z, h3 = rs3 * hv.w;
        float4 r;
        r.x = h0 > 0.f ? h0 : expm1f(h0);
        r.y = h1 > 0.f ? h1 : expm1f(h1);
        r.z = h2 > 0.f ? h2 : expm1f(h2);
        r.w = h3 > 0.f ? h3 : expm1f(h3);
        *(float4*)(out + kAttElems +
                   ((long long)(b * kN + i) * kT + t) * kC + lg * 4) = r;
    }
}

extern "C" void kernel_launch(void* const* d_in, const int* in_sizes, int n_in,
                              void* d_out, int out_size) {
    const float* x   = (const float*)d_in[0];
    const float* adj = (const float*)d_in[1];
    const float* W   = (const float*)d_in[2];
    float* out = (float*)d_out;

    h_kernel<<<(kRows * kC) / 256, 256>>>(x, W);

    dim3 grid(kB * kNP * kP, kN / 8);   // (192, 8)
    att_kernel<<<grid, 256>>>(adj, out);
}

// round 4
// speedup vs baseline: 2.2816x; 1.0692x over previous
#include <cuda_runtime.h>

namespace {
constexpr int kB = 2, kNP = 4, kN = 64, kP = 24, kCin = 16, kC = 32, kT = 96;
constexpr int kRows = kB * kNP * kN * kP;                                // 12288
constexpr long long kAttElems = (long long)kB * kN * kN * kT * kC;       // 25165824
constexpr int kPad = 36;          // smem row stride (floats), 16B-aligned
constexpr float kLog2e = 1.4426950408889634f;
}

__device__ float g_h[kRows * kC];   // h = x @ W, (B*6144, 32) row-major

__device__ __forceinline__ float ex2f(float x) {
    float r; asm("ex2.approx.f32 %0, %1;" : "=f"(r) : "f"(x)); return r;
}
__device__ __forceinline__ float rcpf(float x) {
    float r; asm("rcp.approx.f32 %0, %1;" : "=f"(r) : "f"(x)); return r;
}

// Kernel 1: h[row, c] = sum_k x[row, k] * W[k, c]
__global__ void h_kernel(const float* __restrict__ x, const float* __restrict__ W) {
    int gid = blockIdx.x * 256 + threadIdx.x;
    int c = gid & 31;
    int row = gid >> 5;
    const float4* xr = (const float4*)(x + row * kCin);
    float4 a0 = __ldg(xr), a1 = __ldg(xr + 1), a2 = __ldg(xr + 2), a3 = __ldg(xr + 3);
    float acc = 0.f;
    acc = fmaf(a0.x, __ldg(W +  0 * kC + c), acc);
    acc = fmaf(a0.y, __ldg(W +  1 * kC + c), acc);
    acc = fmaf(a0.z, __ldg(W +  2 * kC + c), acc);
    acc = fmaf(a0.w, __ldg(W +  3 * kC + c), acc);
    acc = fmaf(a1.x, __ldg(W +  4 * kC + c), acc);
    acc = fmaf(a1.y, __ldg(W +  5 * kC + c), acc);
    acc = fmaf(a1.z, __ldg(W +  6 * kC + c), acc);
    acc = fmaf(a1.w, __ldg(W +  7 * kC + c), acc);
    acc = fmaf(a2.x, __ldg(W +  8 * kC + c), acc);
    acc = fmaf(a2.y, __ldg(W +  9 * kC + c), acc);
    acc = fmaf(a2.z, __ldg(W + 10 * kC + c), acc);
    acc = fmaf(a2.w, __ldg(W + 11 * kC + c), acc);
    acc = fmaf(a3.x, __ldg(W + 12 * kC + c), acc);
    acc = fmaf(a3.y, __ldg(W + 13 * kC + c), acc);
    acc = fmaf(a3.z, __ldg(W + 14 * kC + c), acc);
    acc = fmaf(a3.w, __ldg(W + 15 * kC + c), acc);
    g_h[gid] = acc;
}

// Kernel 2: warp = (b,s,i,p); 8-lane group owns one j (4 j's per iter);
// lane owns 4 channels. adj pre-scaled by log2e (and 0.2*log2e) at staging so
// the inner loop is: x=hi*hj; max(x*A1,x*A2); ex2; shfl-sum(8); rcp; store.
__global__ void __launch_bounds__(256)
att_kernel(const float* __restrict__ adj, float* __restrict__ out) {
    __shared__ float  hs[kN * kPad];   // 64 rows of h[b,s,j,p,:]
    __shared__ float2 as2[8 * kN];     // (adj*log2e, 0.2*adj*log2e) per (i,j)

    const int tid  = threadIdx.x;
    const int warp = tid >> 5;
    const int lane = tid & 31;
    const int lg   = lane & 7;         // channel group: c = 4*lg..4*lg+3
    const int grp  = lane >> 3;        // j subgroup within warp

    const int p  = blockIdx.x % kP;
    const int bs = blockIdx.x / kP;
    const int s  = bs & 3;
    const int b  = bs >> 2;
    const int i0 = (int)blockIdx.y * 8;
    const int i  = i0 + warp;

    // Stage h rows (512 float4); row j lives at +j*768 floats in g_h
    const float4* hb = (const float4*)(g_h + (b * 6144 + s * 1536 + p) * 32);
#pragma unroll
    for (int r = 0; r < 2; ++r) {
        int idx = tid + r * 256;            // 0..511
        int jj = idx >> 3, q = idx & 7;
        *(float4*)(hs + jj * kPad + q * 4) = __ldg(hb + jj * 192 + q);
    }
    // Stage pre-scaled adjacency for this block's 8 i's
#pragma unroll
    for (int r = 0; r < 2; ++r) {
        int idx = tid + r * 256;
        float a = __ldg(adj + (i0 + (idx >> 6)) * kN + (idx & 63));
        float a1 = a * kLog2e;
        as2[idx] = make_float2(a1, 0.2f * a1);
    }
    __syncthreads();

    const float4 hiv = *(const float4*)(hs + i * kPad + lg * 4);

    const int t = p * kNP + s;
    float* ob = out + (((long long)(b * kN + i) * kN) * kT + t) * kC;

    float rs0 = 0.f, rs1 = 0.f, rs2 = 0.f, rs3 = 0.f;
#pragma unroll
    for (int jg = 0; jg < 16; ++jg) {
        const int j = jg * 4 + grp;
        const float4 hj = *(const float4*)(hs + j * kPad + lg * 4);
        const float2 A = as2[warp * kN + j];
        float x0 = hiv.x * hj.x, x1 = hiv.y * hj.y;
        float x2 = hiv.z * hj.z, x3 = hiv.w * hj.w;
        float m0 = fmaxf(x0 * A.x, x0 * A.y);
        float m1 = fmaxf(x1 * A.x, x1 * A.y);
        float m2 = fmaxf(x2 * A.x, x2 * A.y);
        float m3 = fmaxf(x3 * A.x, x3 * A.y);
        float e0 = ex2f(m0), e1 = ex2f(m1), e2 = ex2f(m2), e3 = ex2f(m3);
        float sl = (e0 + e1) + (e2 + e3);
        sl += __shfl_xor_sync(0xffffffffu, sl, 1);
        sl += __shfl_xor_sync(0xffffffffu, sl, 2);
        sl += __shfl_xor_sync(0xffffffffu, sl, 4);
        const float inv = rcpf(sl);
        float4 o;
        o.x = e0 * inv; o.y = e1 * inv; o.z = e2 * inv; o.w = e3 * inv;
        rs0 += o.x; rs1 += o.y; rs2 += o.z; rs3 += o.w;
        *(float4*)(ob + j * (kT * kC) + lg * 4) = o;    // full 128B line per j
    }

    // Reduce rsum across the 4 j-subgroups (lane bits 3,4)
    rs0 += __shfl_xor_sync(0xffffffffu, rs0, 8);
    rs1 += __shfl_xor_sync(0xffffffffu, rs1, 8);
    rs2 += __shfl_xor_sync(0xffffffffu, rs2, 8);
    rs3 += __shfl_xor_sync(0xffffffffu, rs3, 8);
    rs0 += __shfl_xor_sync(0xffffffffu, rs0, 16);
    rs1 += __shfl_xor_sync(0xffffffffu, rs1, 16);
    rs2 += __shfl_xor_sync(0xffffffffu, rs2, 16);
    rs3 += __shfl_xor_sync(0xffffffffu, rs3, 16);

    if (grp == 0) {   // lanes 0..7 hold full sums for channels 4*lg..4*lg+3
        const int sh = t / kP, ph = t % kP;     // h_flat decomposition of t
        const float4 hv = *(const float4*)(g_h +
            (b * 6144 + sh * 1536 + i * kP + ph) * 32 + lg * 4);
        float h0 = rs0 * hv.x, h1 = rs1 * hv.y, h2 = rs2 * hv.z, h3 = rs3 * hv.w;
        float4 r;
        r.x = h0 > 0.f ? h0 : expm1f(h0);
        r.y = h1 > 0.f ? h1 : expm1f(h1);
        r.z = h2 > 0.f ? h2 : expm1f(h2);
        r.w = h3 > 0.f ? h3 : expm1f(h3);
        *(float4*)(out + kAttElems +
                   ((long long)(b * kN + i) * kT + t) * kC + lg * 4) = r;
    }
}

extern "C" void kernel_launch(void* const* d_in, const int* in_sizes, int n_in,
                              void* d_out, int out_size) {
    const float* x   = (const float*)d_in[0];
    const float* adj = (const float*)d_in[1];
    const float* W   = (const float*)d_in[2];
    float* out = (float*)d_out;

    h_kernel<<<(kRows * kC) / 256, 256>>>(x, W);

    dim3 grid(kB * kNP * kP, kN / 8);   // (192, 8)
    att_kernel<<<grid, 256>>>(adj, out);
}